// round 13
// baseline (speedup 1.0000x reference)
#include <cuda_runtime.h>
#include <cuda_bf16.h>
#include <cuda_fp16.h>
#include <math.h>
#include <stdint.h>

// ---------------- static device scratch ----------------
static __device__ float g_x2 [4096*1024];
static __device__ float g_wm0[8388608];
static __device__ float g_wm1[8388608];
static __device__ int   g_sel[4];
static __device__ float g_coef[4];
static __device__ __half g_ah[4194304];
static __device__ __half g_gh[16777216];
static __device__ __half g_wh[4194304];
static __device__ __half g_who[1048576];
static __device__ __half g_wfch[4194304];
static __device__ __half g_wpjh[4194304];
static __device__ __half g_yh[4194304];
static __device__ __half g_qh[4194304];
static __device__ __half g_kh[1048576];
static __device__ __half g_vh[1048576];

// ---------------- PTX helpers ----------------
__device__ __forceinline__ uint32_t smem_u32(const void* p) {
    uint32_t a;
    asm("{ .reg .u64 t; cvta.to.shared.u64 t, %1; cvt.u32.u64 %0, t; }" : "=r"(a) : "l"(p));
    return a;
}
#define CP_ASYNC16(dst, src) \
    asm volatile("cp.async.cg.shared.global [%0], [%1], 16;" :: "r"(dst), "l"(src))
#define CP_COMMIT() asm volatile("cp.async.commit_group;" ::: "memory")
#define CP_WAIT1()  asm volatile("cp.async.wait_group 1;" ::: "memory")
#define CP_WAIT0()  asm volatile("cp.async.wait_group 0;" ::: "memory")

#define LDSM_X4(r, addr) \
    asm volatile("ldmatrix.sync.aligned.m8n8.x4.shared.b16 {%0,%1,%2,%3}, [%4];" \
        : "=r"((r)[0]), "=r"((r)[1]), "=r"((r)[2]), "=r"((r)[3]) : "r"(addr))
#define LDSM_X4_T(r, addr) \
    asm volatile("ldmatrix.sync.aligned.m8n8.x4.trans.shared.b16 {%0,%1,%2,%3}, [%4];" \
        : "=r"((r)[0]), "=r"((r)[1]), "=r"((r)[2]), "=r"((r)[3]) : "r"(addr))

#define MMA_FP16(d, a, b0, b1) \
    asm volatile("mma.sync.aligned.m16n8k16.row.col.f32.f16.f16.f32 " \
        "{%0,%1,%2,%3}, {%4,%5,%6,%7}, {%8,%9}, {%0,%1,%2,%3};" \
        : "+f"((d)[0]), "+f"((d)[1]), "+f"((d)[2]), "+f"((d)[3]) \
        : "r"((a)[0]), "r"((a)[1]), "r"((a)[2]), "r"((a)[3]), "r"(b0), "r"(b1))

__device__ __forceinline__ uint32_t pack2h(float v0, float v1) {
    __half h0 = __float2half_rn(v0), h1 = __float2half_rn(v1);
    return (uint32_t)*(uint16_t*)&h0 | ((uint32_t)*(uint16_t*)&h1 << 16);
}

// ---------------- fp32 -> fp16 convert ----------------
__global__ void splith_kernel(const float* __restrict__ src, __half* __restrict__ hi, int n)
{
    int i = (blockIdx.x * blockDim.x + threadIdx.x) * 8;
    if (i >= n) return;
    float4 a = *(const float4*)(src + i);
    float4 b = *(const float4*)(src + i + 4);
    uint4 H;
    H.x = pack2h(a.x, a.y); H.y = pack2h(a.z, a.w);
    H.z = pack2h(b.x, b.y); H.w = pack2h(b.z, b.w);
    *(uint4*)(hi + i) = H;
}

// ---------------- HMMA fp16 GEMM ----------------
#define TST 80
#define REG_BYTES (128 * TST)
#define STG (2 * REG_BYTES)
#define GEMM_SMEM (3 * STG)

__device__ __forceinline__ void gemm_load_stage(
    uint32_t smbase, int kt, int NT, int K, int tid,
    const __half* s0, const __half* s2)
{
    if (kt < NT) {
        uint32_t sb = smbase + (kt % 3) * STG;
        int k0 = kt * 32;
#pragma unroll
        for (int t = 0; t < 4; t++) {
            int idx = tid + 256 * t;
            int region = idx >> 9;
            int cc = idx & 511;
            int row = cc >> 2, ch = cc & 3;
            uint32_t dst = sb + region * REG_BYTES + row * TST + ch * 16;
            const __half* src = (region ? s2 : s0) + (size_t)row * K + k0 + ch * 8;
            CP_ASYNC16(dst, src);
        }
    }
    CP_COMMIT();
}

// mode 0: C fp32 (+res); mode 1: relu^2 -> fp16; mode 2: fused qkv prep
__global__ __launch_bounds__(256, 2) void gemm_fp16(
    const __half* __restrict__ Ah, const __half* __restrict__ Wh,
    float* __restrict__ C, const float* __restrict__ res, int N, int K,
    __half* __restrict__ OH, int mode,
    __half* __restrict__ qh, __half* __restrict__ kh, __half* __restrict__ vh,
    const float* __restrict__ qg, const float* __restrict__ kg)
{
    extern __shared__ char smem[];
    uint32_t smbase = smem_u32(smem);
    int tid = threadIdx.x, wid = tid >> 5, lane = tid & 31;
    int m0 = blockIdx.y * 128, n0 = blockIdx.x * 128;
    int wm = wid >> 1, wn = wid & 1;

    const __half* s0 = Ah + (size_t)m0 * K;
    const __half* s2 = Wh + (size_t)n0 * K;

    float acc[2][8][4];
#pragma unroll
    for (int i = 0; i < 2; i++)
#pragma unroll
        for (int j = 0; j < 8; j++)
#pragma unroll
            for (int r = 0; r < 4; r++) acc[i][j][r] = 0.f;

    int NT = K >> 5;
    gemm_load_stage(smbase, 0, NT, K, tid, s0, s2);
    gemm_load_stage(smbase, 1, NT, K, tid, s0, s2);

    int lt = lane >> 3, lr = lane & 7;
    for (int kt = 0; kt < NT; kt++) {
        CP_WAIT1();
        __syncthreads();
        gemm_load_stage(smbase, kt + 2, NT, K, tid, s0, s2);
        uint32_t sb = smbase + (kt % 3) * STG;
        uint32_t sbW = sb + REG_BYTES;
#pragma unroll
        for (int kk = 0; kk < 2; kk++) {
            uint32_t a_hi[2][4];
#pragma unroll
            for (int i = 0; i < 2; i++) {
                int row = wm * 32 + i * 16 + lr + (lt & 1) * 8;
                int kofs = kk * 16 + (lt >> 1) * 8;
                LDSM_X4(a_hi[i], sb + row * TST + kofs * 2);
            }
            uint32_t b_hi[4][4];
#pragma unroll
            for (int j = 0; j < 4; j++) {
                int row = wn * 64 + j * 16 + lr + (lt >> 1) * 8;
                int kofs = kk * 16 + (lt & 1) * 8;
                LDSM_X4(b_hi[j], sbW + row * TST + kofs * 2);
            }
#pragma unroll
            for (int i = 0; i < 2; i++)
#pragma unroll
                for (int j = 0; j < 8; j++) {
                    MMA_FP16(acc[i][j], a_hi[i],
                             b_hi[j >> 1][(j & 1) * 2], b_hi[j >> 1][(j & 1) * 2 + 1]);
                }
        }
    }
    CP_WAIT0();

    int rbase = m0 + wm * 32 + (lane >> 2);
    int cbase = n0 + wn * 64 + (lane & 3) * 2;

    if (mode == 2) {
        int hd = blockIdx.x * 2 + wn;
#pragma unroll
        for (int i = 0; i < 2; i++) {
#pragma unroll
            for (int half = 0; half < 2; half++) {
                int m = rbase + i * 16 + half * 8;
                int t = m & 2047, bb = m >> 11;
                float vals[8][2];
#pragma unroll
                for (int j = 0; j < 8; j++) {
                    vals[j][0] = acc[i][j][half * 2 + 0];
                    vals[j][1] = acc[i][j][half * 2 + 1];
                }
                if (hd < 20) {
                    float ss = 0.f;
#pragma unroll
                    for (int j = 0; j < 8; j++) ss += vals[j][0]*vals[j][0] + vals[j][1]*vals[j][1];
                    ss += __shfl_xor_sync(0xffffffffu, ss, 1);
                    ss += __shfl_xor_sync(0xffffffffu, ss, 2);
                    float gain = (hd < 16) ? qg[hd] : kg[hd - 16];
                    float r = rsqrtf(ss * (1.f/64.f) + 1e-6f) * gain;
#pragma unroll
                    for (int j = 0; j < 4; j++) {
                        float o1[2], o2[2];
#pragma unroll
                        for (int s = 0; s < 2; s++) {
                            int p = (lane & 3) * 2 + j * 8 + s;
                            float ang = (float)t * exp2f(-0.41524101186092029f * (float)p);
                            float sn, cs;
                            sincosf(ang, &sn, &cs);
                            float v1 = vals[j][s] * r, v2 = vals[j + 4][s] * r;
                            o1[s] = v1 * cs + v2 * sn;
                            o2[s] = v2 * cs - v1 * sn;
                        }
                        int c0 = (lane & 3) * 2 + j * 8;
                        if (hd < 16) {
                            size_t base = ((size_t)(bb * 16 + hd) * 2048 + t) * 64;
                            *(uint32_t*)(qh + base + c0)      = pack2h(o1[0], o1[1]);
                            *(uint32_t*)(qh + base + c0 + 32) = pack2h(o2[0], o2[1]);
                        } else {
                            size_t base = ((size_t)(bb * 4 + hd - 16) * 2048 + t) * 64;
                            *(uint32_t*)(kh + base + c0)      = pack2h(o1[0], o1[1]);
                            *(uint32_t*)(kh + base + c0 + 32) = pack2h(o2[0], o2[1]);
                        }
                    }
                } else {
                    size_t base = ((size_t)(bb * 4 + hd - 20) * 2048 + t) * 64;
#pragma unroll
                    for (int j = 0; j < 8; j++) {
                        int c0 = (lane & 3) * 2 + j * 8;
                        *(uint32_t*)(vh + base + c0) = pack2h(vals[j][0], vals[j][1]);
                    }
                }
            }
        }
        return;
    }

#pragma unroll
    for (int i = 0; i < 2; i++) {
#pragma unroll
        for (int half = 0; half < 2; half++) {
            size_t row = (size_t)(rbase + i * 16 + half * 8);
#pragma unroll
            for (int j = 0; j < 8; j++) {
                size_t idx = row * (size_t)N + cbase + j * 8;
                float v0 = acc[i][j][half * 2 + 0];
                float v1 = acc[i][j][half * 2 + 1];
                if (mode == 1) {
                    v0 = fmaxf(v0, 0.f); v0 *= v0;
                    v1 = fmaxf(v1, 0.f); v1 *= v1;
                    *(uint32_t*)(OH + idx) = pack2h(v0, v1);
                } else {
                    if (res) { v0 += res[idx]; v1 += res[idx + 1]; }
                    *(float2*)(C + idx) = make_float2(v0, v1);
                }
            }
        }
    }
}

// ---------------- RMSNorm with fp16 output ----------------
__global__ void rmsnorm_h_kernel(const float* __restrict__ x, __half* __restrict__ hi)
{
    int n = blockIdx.x;
    int tid = threadIdx.x;
    const float4* xr = (const float4*)(x + (size_t)n * 1024);
    float4 v = xr[tid];
    float s = v.x*v.x + v.y*v.y + v.z*v.z + v.w*v.w;
#pragma unroll
    for (int off = 16; off > 0; off >>= 1) s += __shfl_xor_sync(0xffffffffu, s, off);
    __shared__ float red[8];
    if ((tid & 31) == 0) red[tid >> 5] = s;
    __syncthreads();
    float tot = 0.f;
#pragma unroll
    for (int i = 0; i < 8; i++) tot += red[i];
    float r = rsqrtf(tot * (1.f/1024.f) + 1e-6f);
    size_t base = (size_t)n * 1024 + tid * 4;
    *(uint2*)(hi + base) = make_uint2(pack2h(v.x*r, v.y*r), pack2h(v.z*r, v.w*r));
}

// ---------------- tensor-core flash attention (fp16, Q tile = 128 rows) ----------------
#define AT_ROWB 144
#define AT_TILE (64 * AT_ROWB)           // 9216
#define AQ_BYTES (2 * AT_TILE)           // Q: 128 rows = 18432
#define AT_STAGE (2 * AT_TILE)           // K + V tiles
#define ATTN_SMEM (AQ_BYTES + 2 * AT_STAGE)  // 55296

__device__ __forceinline__ void attn_load_kv(
    uint32_t dstbase, int tid,
    const __half* kh, const __half* vh, size_t kvoff, int kt)
{
#pragma unroll
    for (int t = 0; t < 4; t++) {
        int idx = tid + 256 * t;                 // 0..1023
        int buf = idx >> 9, cc = idx & 511, row = cc >> 3, ch = cc & 7;
        const __half* src = (buf ? vh : kh) + kvoff + (size_t)(kt * 64 + row) * 64 + ch * 8;
        CP_ASYNC16(dstbase + buf * AT_TILE + row * AT_ROWB + ch * 16, src);
    }
}

__global__ __launch_bounds__(256) void attn_mma_kernel(
    const __half* __restrict__ qh,
    const __half* __restrict__ kh, const __half* __restrict__ vh,
    __half* __restrict__ yh)
{
    extern __shared__ char smem[];
    uint32_t sb = smem_u32(smem);
    int qt = gridDim.x - 1 - blockIdx.x;        // 0..15, heavy first
    int h = blockIdx.y, b = blockIdx.z;
    int tid = threadIdx.x, w = tid >> 5, lane = tid & 31;
    int lr = lane & 7, lt = lane >> 3;
    size_t qoff = ((size_t)(b * 16 + h) * 2048 + qt * 128) * 64;
    size_t kvoff = (size_t)(b * 4 + (h >> 2)) * 2048 * 64;

    // load Q tile (128 rows)
#pragma unroll
    for (int t = 0; t < 4; t++) {
        int idx = tid + 256 * t;                 // 0..1023
        int row = idx >> 3, ch = idx & 7;
        CP_ASYNC16(sb + row * AT_ROWB + ch * 16, qh + qoff + row * 64 + ch * 8);
    }
    CP_COMMIT();
    attn_load_kv(sb + AQ_BYTES, tid, kh, vh, kvoff, 0);
    CP_COMMIT();
    CP_WAIT0();
    __syncthreads();

    uint32_t qfh[4][4];
#pragma unroll
    for (int kk = 0; kk < 4; kk++) {
        uint32_t addr = sb + (w * 16 + lr + (lt & 1) * 8) * AT_ROWB + (kk * 16 + (lt >> 1) * 8) * 2;
        LDSM_X4(qfh[kk], addr);
    }

    float O[8][4];
#pragma unroll
    for (int j = 0; j < 8; j++)
#pragma unroll
        for (int r = 0; r < 4; r++) O[j][r] = 0.f;
    float m0 = -1e30f, m1 = -1e30f, l0 = 0.f, l1 = 0.f;

    int ktmax = 2 * qt + 1;
    int grow0 = qt * 128 + w * 16 + (lane >> 2);
    int grow1 = grow0 + 8;

    for (int kt = 0; kt <= ktmax; kt++) {
        if (kt < ktmax) {
            attn_load_kv(sb + AQ_BYTES + ((kt + 1) & 1) * AT_STAGE, tid, kh, vh, kvoff, kt + 1);
            CP_COMMIT();
        }
        uint32_t kb = sb + AQ_BYTES + (kt & 1) * AT_STAGE;
        float c[8][4];
#pragma unroll
        for (int j = 0; j < 8; j++)
#pragma unroll
            for (int r = 0; r < 4; r++) c[j][r] = 0.f;
#pragma unroll
        for (int kk = 0; kk < 4; kk++) {
            uint32_t kbh[4][4];
#pragma unroll
            for (int j2 = 0; j2 < 4; j2++) {
                uint32_t addr = kb + (j2 * 16 + lr + (lt >> 1) * 8) * AT_ROWB + (kk * 16 + (lt & 1) * 8) * 2;
                LDSM_X4(kbh[j2], addr);
            }
#pragma unroll
            for (int j = 0; j < 8; j++) {
                MMA_FP16(c[j], qfh[kk], kbh[j >> 1][(j & 1) * 2], kbh[j >> 1][(j & 1) * 2 + 1]);
            }
        }
        if (kt >= 2 * qt) {
#pragma unroll
            for (int j = 0; j < 8; j++) {
                int gcol = kt * 64 + j * 8 + (lane & 3) * 2;
                if (gcol     > grow0) c[j][0] = -1e30f;
                if (gcol + 1 > grow0) c[j][1] = -1e30f;
                if (gcol     > grow1) c[j][2] = -1e30f;
                if (gcol + 1 > grow1) c[j][3] = -1e30f;
            }
        }
        float mx0 = -1e30f, mx1 = -1e30f;
#pragma unroll
        for (int j = 0; j < 8; j++) {
            mx0 = fmaxf(mx0, fmaxf(c[j][0], c[j][1]));
            mx1 = fmaxf(mx1, fmaxf(c[j][2], c[j][3]));
        }
        mx0 *= 0.125f; mx1 *= 0.125f;
        mx0 = fmaxf(mx0, __shfl_xor_sync(0xffffffffu, mx0, 1));
        mx0 = fmaxf(mx0, __shfl_xor_sync(0xffffffffu, mx0, 2));
        mx1 = fmaxf(mx1, __shfl_xor_sync(0xffffffffu, mx1, 1));
        mx1 = fmaxf(mx1, __shfl_xor_sync(0xffffffffu, mx1, 2));
        float m0n = fmaxf(m0, mx0), m1n = fmaxf(m1, mx1);
        float cr0 = __expf(m0 - m0n), cr1 = __expf(m1 - m1n);
        float s0 = 0.f, s1 = 0.f;
#pragma unroll
        for (int j = 0; j < 8; j++) {
            c[j][0] = __expf(fmaf(c[j][0], 0.125f, -m0n)); s0 += c[j][0];
            c[j][1] = __expf(fmaf(c[j][1], 0.125f, -m0n)); s0 += c[j][1];
            c[j][2] = __expf(fmaf(c[j][2], 0.125f, -m1n)); s1 += c[j][2];
            c[j][3] = __expf(fmaf(c[j][3], 0.125f, -m1n)); s1 += c[j][3];
        }
        s0 += __shfl_xor_sync(0xffffffffu, s0, 1);
        s0 += __shfl_xor_sync(0xffffffffu, s0, 2);
        s1 += __shfl_xor_sync(0xffffffffu, s1, 1);
        s1 += __shfl_xor_sync(0xffffffffu, s1, 2);
        l0 = l0 * cr0 + s0; l1 = l1 * cr1 + s1;
        m0 = m0n; m1 = m1n;
#pragma unroll
        for (int j = 0; j < 8; j++) {
            O[j][0] *= cr0; O[j][1] *= cr0;
            O[j][2] *= cr1; O[j][3] *= cr1;
        }
#pragma unroll
        for (int kt2 = 0; kt2 < 4; kt2++) {
            uint32_t pah[4];
            pah[0] = pack2h(c[2*kt2][0],   c[2*kt2][1]);
            pah[1] = pack2h(c[2*kt2][2],   c[2*kt2][3]);
            pah[2] = pack2h(c[2*kt2+1][0], c[2*kt2+1][1]);
            pah[3] = pack2h(c[2*kt2+1][2], c[2*kt2+1][3]);
#pragma unroll
            for (int jd = 0; jd < 4; jd++) {
                uint32_t vbh[4];
                uint32_t addr = kb + AT_TILE + (kt2 * 16 + (lt & 1) * 8 + lr) * AT_ROWB + (jd * 16 + (lt >> 1) * 8) * 2;
                LDSM_X4_T(vbh, addr);
#pragma unroll
                for (int js = 0; js < 2; js++) {
                    MMA_FP16(O[jd * 2 + js], pah, vbh[js*2], vbh[js*2+1]);
                }
            }
        }
        if (kt < ktmax) CP_WAIT0();
        __syncthreads();
    }
    float i0 = 1.f / l0, i1 = 1.f / l1;
    size_t rA = (size_t)(b * 2048 + qt * 128 + w * 16 + (lane >> 2));
    size_t rB = rA + 8;
    int colb = h * 64 + (lane & 3) * 2;
#pragma unroll
    for (int j = 0; j < 8; j++) {
        int col = colb + j * 8;
        *(uint32_t*)(yh + rA * 1024 + col) = pack2h(O[j][0] * i0, O[j][1] * i0);
        *(uint32_t*)(yh + rB * 1024 + col) = pack2h(O[j][2] * i1, O[j][3] * i1);
    }
}

// ---------------- tile helpers for folding kernels ----------------
#define TP 68
__device__ __forceinline__ void load_tile_s(float* dst, const float* src, size_t stride, int tid) {
#pragma unroll
    for (int r = 0; r < 4; r++) {
        int f = tid + 256 * r;
        int row = f >> 4, c4 = (f & 15) << 2;
        *(float4*)&dst[row*TP + c4] = *(const float4*)(src + (size_t)row * stride + c4);
    }
}
__device__ __forceinline__ void load_tileT_s(float* dst, const float* src, size_t stride, int tid) {
#pragma unroll
    for (int r = 0; r < 4; r++) {
        int f = tid + 256 * r;
        int row = f >> 4, c4 = (f & 15) << 2;
        float4 v = *(const float4*)(src + (size_t)row * stride + c4);
        dst[(c4+0)*TP + row] = v.x; dst[(c4+1)*TP + row] = v.y;
        dst[(c4+2)*TP + row] = v.z; dst[(c4+3)*TP + row] = v.w;
    }
}
__device__ __forceinline__ void mm64(const float* XT, const float* W, float acc[4][4], int tx, int ty) {
#pragma unroll
    for (int c = 0; c < 64; c++) {
        float a[4], bb[4];
        *(float4*)a  = *(const float4*)&XT[c*TP + ty*4];
        *(float4*)bb = *(const float4*)&W [c*TP + tx*4];
#pragma unroll
        for (int i = 0; i < 4; i++)
#pragma unroll
            for (int j = 0; j < 4; j++) acc[i][j] = fmaf(a[i], bb[j], acc[i][j]);
    }
}

// ---------------- P1: fold s2 into mix ----------------
__global__ __launch_bounds__(256) void fold1_kernel(
    const float* __restrict__ Mix, const float* __restrict__ S2,
    float* __restrict__ WM2T, int in_f, int out_f,
    const int* __restrict__ selp)
{
    extern __shared__ float sm[];
    float* MT = sm;
    float* S  = sm + 4352;
    int jb = blockIdx.x, G = blockIdx.y, r = blockIdx.z;
    int sel = selp[r];
    int tid = threadIdx.x;
    load_tile_s(MT, Mix + (size_t)sel * out_f * in_f + (size_t)(G * 64) * in_f + jb * 64, in_f, tid);
    load_tile_s(S,  S2  + (size_t)sel * out_f * 64 + (size_t)G * 4096, 64, tid);
    __syncthreads();
    int tx = tid & 15, ty = tid >> 4;
    float acc[4][4] = {};
    mm64(MT, S, acc, tx, ty);
    float* outp = WM2T + (size_t)r * in_f * out_f;
#pragma unroll
    for (int i = 0; i < 4; i++) {
        size_t row = (size_t)(jb * 64 + ty * 4 + i);
        *(float4*)(outp + row * out_f + G * 64 + tx * 4) =
            make_float4(acc[i][0], acc[i][1], acc[i][2], acc[i][3]);
    }
}

// ---------------- P2: fold s1 + roll-perm, combine experts, fp16 out ----------------
__global__ __launch_bounds__(256) void fold2_kernel(
    const float* __restrict__ WM2T, const float* __restrict__ S1,
    __half* __restrict__ WH,
    int in_f, int out_f, int n_in,
    const int* __restrict__ selp, const float* __restrict__ coefp)
{
    extern __shared__ float sm[];
    float* G0 = sm;
    float* G1 = sm + 4352;
    float* T0 = sm + 8704;
    float* T1 = sm + 13056;
    int g = blockIdx.x, Ob = blockIdx.y, tid = threadIdx.x;
    int s0i = selp[0], s1i = selp[1];
    int gs0 = (g + s0i) % n_in, gs1 = (g + s1i) % n_in;
    const float* W0 = WM2T;
    const float* W1 = WM2T + (size_t)in_f * out_f;
#pragma unroll
    for (int r = 0; r < 4; r++) {
        int f = tid + 256 * r;
        int d = f >> 4, o4 = (f & 15) << 2;
        *(float4*)&G0[d*TP + o4] = *(const float4*)(W0 + (size_t)(d * n_in + gs0) * out_f + Ob * 64 + o4);
        *(float4*)&G1[d*TP + o4] = *(const float4*)(W1 + (size_t)(d * n_in + gs1) * out_f + Ob * 64 + o4);
    }
    load_tileT_s(T0, S1 + (size_t)s0i * in_f * 64 + (size_t)g * 4096, 64, tid);
    load_tileT_s(T1, S1 + (size_t)s1i * in_f * 64 + (size_t)g * 4096, 64, tid);
    __syncthreads();
    int tx = tid & 15, ty = tid >> 4;
    float a0[4][4] = {}, a1[4][4] = {};
    mm64(G0, T0, a0, tx, ty);
    mm64(G1, T1, a1, tx, ty);
    float c0 = coefp[0], c1 = coefp[1];
#pragma unroll
    for (int i = 0; i < 4; i++) {
        size_t base = (size_t)(Ob * 64 + ty * 4 + i) * in_f + g * 64 + tx * 4;
        float v0 = c0 * a0[i][0] + c1 * a1[i][0];
        float v1 = c0 * a0[i][1] + c1 * a1[i][1];
        float v2 = c0 * a0[i][2] + c1 * a1[i][2];
        float v3 = c0 * a0[i][3] + c1 * a1[i][3];
        *(uint32_t*)(WH + base)     = pack2h(v0, v1);
        *(uint32_t*)(WH + base + 2) = pack2h(v2, v3);
    }
}

// ---------------- top-2 router ----------------
__global__ void router_kernel(const float* __restrict__ fcl, const float* __restrict__ pjl,
                              int* __restrict__ sel, float* __restrict__ coef)
{
    if (threadIdx.x == 0 && blockIdx.x == 0) {
#pragma unroll
        for (int s = 0; s < 2; s++) {
            const float* L = s ? pjl : fcl;
            int i1 = 0; float v1 = L[0];
            for (int i = 1; i < 8; i++) if (L[i] > v1) { v1 = L[i]; i1 = i; }
            int i2 = -1; float v2 = -1e30f;
            for (int i = 0; i < 8; i++) if (i != i1 && L[i] > v2) { v2 = L[i]; i2 = i; }
            float e = expf(v2 - v1);
            float z = 1.f + e;
            sel[s*2+0] = i1; sel[s*2+1] = i2;
            coef[s*2+0] = 1.f / z; coef[s*2+1] = e / z;
        }
    }
}

// ---------------- host orchestration ----------------
#define FOLD1_SMEM (8704 * 4)
#define FOLD2_SMEM (17408 * 4)

extern "C" void kernel_launch(void* const* d_in, const int* in_sizes, int n_in_,
                              void* d_out, int out_size)
{
    (void)in_sizes; (void)n_in_; (void)out_size;
    const float* x      = (const float*)d_in[0];
    const float* wq     = (const float*)d_in[1];
    const float* wk     = (const float*)d_in[2];
    const float* wv     = (const float*)d_in[3];
    const float* wo     = (const float*)d_in[4];
    const float* qg     = (const float*)d_in[5];
    const float* kg     = (const float*)d_in[6];
    const float* fc_s1  = (const float*)d_in[7];
    const float* fc_s2  = (const float*)d_in[8];
    const float* fc_mix = (const float*)d_in[9];
    const float* fc_lg  = (const float*)d_in[10];
    const float* pj_s1  = (const float*)d_in[11];
    const float* pj_s2  = (const float*)d_in[12];
    const float* pj_mix = (const float*)d_in[13];
    const float* pj_lg  = (const float*)d_in[14];

    float *x2, *wm0, *wm1, *coef;
    int* sel;
    __half *ah, *gh, *wh, *who, *wfch, *wpjh, *yh, *qh, *kh, *vh;
    cudaGetSymbolAddress((void**)&x2,  g_x2);
    cudaGetSymbolAddress((void**)&wm0, g_wm0);
    cudaGetSymbolAddress((void**)&wm1, g_wm1);
    cudaGetSymbolAddress((void**)&sel,  g_sel);
    cudaGetSymbolAddress((void**)&coef, g_coef);
    cudaGetSymbolAddress((void**)&ah, g_ah);
    cudaGetSymbolAddress((void**)&gh, g_gh);
    cudaGetSymbolAddress((void**)&wh, g_wh);
    cudaGetSymbolAddress((void**)&who, g_who);
    cudaGetSymbolAddress((void**)&wfch, g_wfch);
    cudaGetSymbolAddress((void**)&wpjh, g_wpjh);
    cudaGetSymbolAddress((void**)&yh, g_yh);
    cudaGetSymbolAddress((void**)&qh, g_qh);
    cudaGetSymbolAddress((void**)&kh, g_kh);
    cudaGetSymbolAddress((void**)&vh, g_vh);

    cudaFuncSetAttribute(gemm_fp16, cudaFuncAttributeMaxDynamicSharedMemorySize, GEMM_SMEM);
    cudaFuncSetAttribute(attn_mma_kernel, cudaFuncAttributeMaxDynamicSharedMemorySize, ATTN_SMEM);
    cudaFuncSetAttribute(fold1_kernel, cudaFuncAttributeMaxDynamicSharedMemorySize, FOLD1_SMEM);
    cudaFuncSetAttribute(fold2_kernel, cudaFuncAttributeMaxDynamicSharedMemorySize, FOLD2_SMEM);

    static cudaStream_t s2 = nullptr;
    static cudaEvent_t ev_fork = nullptr, ev_wqkv = nullptr, ev_wo = nullptr, ev_fold = nullptr;
    if (!s2) {
        cudaStreamCreateWithFlags(&s2, cudaStreamNonBlocking);
        cudaEventCreateWithFlags(&ev_fork, cudaEventDisableTiming);
        cudaEventCreateWithFlags(&ev_wqkv, cudaEventDisableTiming);
        cudaEventCreateWithFlags(&ev_wo,   cudaEventDisableTiming);
        cudaEventCreateWithFlags(&ev_fold, cudaEventDisableTiming);
    }

    // ---- fork: side stream does weight converts + routing + folding ----
    cudaEventRecord(ev_fork, 0);
    cudaStreamWaitEvent(s2, ev_fork, 0);

    splith_kernel<<<512, 256, 0, s2>>>(wq, wh, 1048576);
    splith_kernel<<<128, 256, 0, s2>>>(wk, wh + 1048576, 262144);
    splith_kernel<<<128, 256, 0, s2>>>(wv, wh + 1310720, 262144);
    cudaEventRecord(ev_wqkv, s2);
    splith_kernel<<<512, 256, 0, s2>>>(wo, who, 1048576);
    cudaEventRecord(ev_wo, s2);
    router_kernel<<<1, 32, 0, s2>>>(fc_lg, pj_lg, sel, coef);
    fold1_kernel<<<dim3(16, 64, 2), 256, FOLD1_SMEM, s2>>>(fc_mix, fc_s2, wm0, 1024, 4096, sel);
    fold2_kernel<<<dim3(16, 64), 256, FOLD2_SMEM, s2>>>(wm0, fc_s1, wfch, 1024, 4096, 16, sel, coef);
    fold1_kernel<<<dim3(64, 16, 2), 256, FOLD1_SMEM, s2>>>(pj_mix, pj_s2, wm1, 4096, 1024, sel + 2);
    fold2_kernel<<<dim3(64, 16), 256, FOLD2_SMEM, s2>>>(wm1, pj_s1, wpjh, 4096, 1024, 64, sel + 2, coef + 2);
    cudaEventRecord(ev_fold, s2);

    // ---- main stream: attention path ----
    rmsnorm_h_kernel<<<4096, 256>>>(x, ah);
    cudaStreamWaitEvent(0, ev_wqkv, 0);
    gemm_fp16<<<dim3(12, 32), 256, GEMM_SMEM>>>(ah, wh, nullptr, nullptr, 1536, 1024,
                                                nullptr, 2, qh, kh, vh, qg, kg);
    attn_mma_kernel<<<dim3(16, 16, 2), 256, ATTN_SMEM>>>(qh, kh, vh, yh);

    cudaStreamWaitEvent(0, ev_wo, 0);
    gemm_fp16<<<dim3(8, 32), 256, GEMM_SMEM>>>(yh, who, x2, x, 1024, 1024,
                                               nullptr, 0, nullptr, nullptr, nullptr, nullptr, nullptr);

    rmsnorm_h_kernel<<<4096, 256>>>(x2, ah);

    cudaStreamWaitEvent(0, ev_fold, 0);
    gemm_fp16<<<dim3(32, 32), 256, GEMM_SMEM>>>(ah, wfch, nullptr, nullptr, 4096, 1024,
                                                gh, 1, nullptr, nullptr, nullptr, nullptr, nullptr);
    gemm_fp16<<<dim3(8, 32), 256, GEMM_SMEM>>>(gh, wpjh, (float*)d_out, x2, 1024, 4096,
                                               nullptr, 0, nullptr, nullptr, nullptr, nullptr, nullptr);
}

// round 14
// speedup vs baseline: 1.1453x; 1.1453x over previous
#include <cuda_runtime.h>
#include <cuda_bf16.h>
#include <cuda_fp16.h>
#include <math.h>
#include <stdint.h>

// ---------------- static device scratch ----------------
static __device__ float g_x2 [4096*1024];
static __device__ __half g_wm0[8388608];     // WM2T fp16, 2 experts (fc)
static __device__ __half g_wm1[8388608];     // WM2T fp16, 2 experts (pj)
static __device__ int   g_sel[4];
static __device__ float g_coef[4];
static __device__ __half g_ah[4194304];
static __device__ __half g_gh[16777216];
static __device__ __half g_wh[4194304];
static __device__ __half g_who[1048576];
static __device__ __half g_wfch[4194304];
static __device__ __half g_wpjh[4194304];
static __device__ __half g_yh[4194304];
static __device__ __half g_qh[4194304];
static __device__ __half g_kh[1048576];
static __device__ __half g_vh[1048576];

// ---------------- PTX helpers ----------------
__device__ __forceinline__ uint32_t smem_u32(const void* p) {
    uint32_t a;
    asm("{ .reg .u64 t; cvta.to.shared.u64 t, %1; cvt.u32.u64 %0, t; }" : "=r"(a) : "l"(p));
    return a;
}
#define CP_ASYNC16(dst, src) \
    asm volatile("cp.async.cg.shared.global [%0], [%1], 16;" :: "r"(dst), "l"(src))
#define CP_COMMIT() asm volatile("cp.async.commit_group;" ::: "memory")
#define CP_WAIT1()  asm volatile("cp.async.wait_group 1;" ::: "memory")
#define CP_WAIT0()  asm volatile("cp.async.wait_group 0;" ::: "memory")

#define LDSM_X4(r, addr) \
    asm volatile("ldmatrix.sync.aligned.m8n8.x4.shared.b16 {%0,%1,%2,%3}, [%4];" \
        : "=r"((r)[0]), "=r"((r)[1]), "=r"((r)[2]), "=r"((r)[3]) : "r"(addr))
#define LDSM_X4_T(r, addr) \
    asm volatile("ldmatrix.sync.aligned.m8n8.x4.trans.shared.b16 {%0,%1,%2,%3}, [%4];" \
        : "=r"((r)[0]), "=r"((r)[1]), "=r"((r)[2]), "=r"((r)[3]) : "r"(addr))

#define MMA_FP16(d, a, b0, b1) \
    asm volatile("mma.sync.aligned.m16n8k16.row.col.f32.f16.f16.f32 " \
        "{%0,%1,%2,%3}, {%4,%5,%6,%7}, {%8,%9}, {%0,%1,%2,%3};" \
        : "+f"((d)[0]), "+f"((d)[1]), "+f"((d)[2]), "+f"((d)[3]) \
        : "r"((a)[0]), "r"((a)[1]), "r"((a)[2]), "r"((a)[3]), "r"(b0), "r"(b1))

__device__ __forceinline__ uint32_t pack2h(float v0, float v1) {
    __half h0 = __float2half_rn(v0), h1 = __float2half_rn(v1);
    return (uint32_t)*(uint16_t*)&h0 | ((uint32_t)*(uint16_t*)&h1 << 16);
}

// ---------------- fp32 -> fp16 convert ----------------
__global__ void splith_kernel(const float* __restrict__ src, __half* __restrict__ hi, int n)
{
    int i = (blockIdx.x * blockDim.x + threadIdx.x) * 8;
    if (i >= n) return;
    float4 a = *(const float4*)(src + i);
    float4 b = *(const float4*)(src + i + 4);
    uint4 H;
    H.x = pack2h(a.x, a.y); H.y = pack2h(a.z, a.w);
    H.z = pack2h(b.x, b.y); H.w = pack2h(b.z, b.w);
    *(uint4*)(hi + i) = H;
}

// ---------------- HMMA fp16 GEMM ----------------
#define TST 80
#define REG_BYTES (128 * TST)
#define STG (2 * REG_BYTES)
#define GEMM_SMEM (3 * STG)

__device__ __forceinline__ void gemm_load_stage(
    uint32_t smbase, int kt, int NT, int K, int tid,
    const __half* s0, const __half* s2)
{
    if (kt < NT) {
        uint32_t sb = smbase + (kt % 3) * STG;
        int k0 = kt * 32;
#pragma unroll
        for (int t = 0; t < 4; t++) {
            int idx = tid + 256 * t;
            int region = idx >> 9;
            int cc = idx & 511;
            int row = cc >> 2, ch = cc & 3;
            uint32_t dst = sb + region * REG_BYTES + row * TST + ch * 16;
            const __half* src = (region ? s2 : s0) + (size_t)row * K + k0 + ch * 8;
            CP_ASYNC16(dst, src);
        }
    }
    CP_COMMIT();
}

// mode 0: C fp32 (+res); mode 1: relu^2 -> fp16; mode 2: fused qkv prep
__global__ __launch_bounds__(256, 2) void gemm_fp16(
    const __half* __restrict__ Ah, const __half* __restrict__ Wh,
    float* __restrict__ C, const float* __restrict__ res, int N, int K,
    __half* __restrict__ OH, int mode,
    __half* __restrict__ qh, __half* __restrict__ kh, __half* __restrict__ vh,
    const float* __restrict__ qg, const float* __restrict__ kg)
{
    extern __shared__ char smem[];
    uint32_t smbase = smem_u32(smem);
    int tid = threadIdx.x, wid = tid >> 5, lane = tid & 31;
    int m0 = blockIdx.y * 128, n0 = blockIdx.x * 128;
    int wm = wid >> 1, wn = wid & 1;

    const __half* s0 = Ah + (size_t)m0 * K;
    const __half* s2 = Wh + (size_t)n0 * K;

    float acc[2][8][4];
#pragma unroll
    for (int i = 0; i < 2; i++)
#pragma unroll
        for (int j = 0; j < 8; j++)
#pragma unroll
            for (int r = 0; r < 4; r++) acc[i][j][r] = 0.f;

    int NT = K >> 5;
    gemm_load_stage(smbase, 0, NT, K, tid, s0, s2);
    gemm_load_stage(smbase, 1, NT, K, tid, s0, s2);

    int lt = lane >> 3, lr = lane & 7;
    for (int kt = 0; kt < NT; kt++) {
        CP_WAIT1();
        __syncthreads();
        gemm_load_stage(smbase, kt + 2, NT, K, tid, s0, s2);
        uint32_t sb = smbase + (kt % 3) * STG;
        uint32_t sbW = sb + REG_BYTES;
#pragma unroll
        for (int kk = 0; kk < 2; kk++) {
            uint32_t a_hi[2][4];
#pragma unroll
            for (int i = 0; i < 2; i++) {
                int row = wm * 32 + i * 16 + lr + (lt & 1) * 8;
                int kofs = kk * 16 + (lt >> 1) * 8;
                LDSM_X4(a_hi[i], sb + row * TST + kofs * 2);
            }
            uint32_t b_hi[4][4];
#pragma unroll
            for (int j = 0; j < 4; j++) {
                int row = wn * 64 + j * 16 + lr + (lt >> 1) * 8;
                int kofs = kk * 16 + (lt & 1) * 8;
                LDSM_X4(b_hi[j], sbW + row * TST + kofs * 2);
            }
#pragma unroll
            for (int i = 0; i < 2; i++)
#pragma unroll
                for (int j = 0; j < 8; j++) {
                    MMA_FP16(acc[i][j], a_hi[i],
                             b_hi[j >> 1][(j & 1) * 2], b_hi[j >> 1][(j & 1) * 2 + 1]);
                }
        }
    }
    CP_WAIT0();

    int rbase = m0 + wm * 32 + (lane >> 2);
    int cbase = n0 + wn * 64 + (lane & 3) * 2;

    if (mode == 2) {
        int hd = blockIdx.x * 2 + wn;
#pragma unroll
        for (int i = 0; i < 2; i++) {
#pragma unroll
            for (int half = 0; half < 2; half++) {
                int m = rbase + i * 16 + half * 8;
                int t = m & 2047, bb = m >> 11;
                float vals[8][2];
#pragma unroll
                for (int j = 0; j < 8; j++) {
                    vals[j][0] = acc[i][j][half * 2 + 0];
                    vals[j][1] = acc[i][j][half * 2 + 1];
                }
                if (hd < 20) {
                    float ss = 0.f;
#pragma unroll
                    for (int j = 0; j < 8; j++) ss += vals[j][0]*vals[j][0] + vals[j][1]*vals[j][1];
                    ss += __shfl_xor_sync(0xffffffffu, ss, 1);
                    ss += __shfl_xor_sync(0xffffffffu, ss, 2);
                    float gain = (hd < 16) ? qg[hd] : kg[hd - 16];
                    float r = rsqrtf(ss * (1.f/64.f) + 1e-6f) * gain;
#pragma unroll
                    for (int j = 0; j < 4; j++) {
                        float o1[2], o2[2];
#pragma unroll
                        for (int s = 0; s < 2; s++) {
                            int p = (lane & 3) * 2 + j * 8 + s;
                            float ang = (float)t * exp2f(-0.41524101186092029f * (float)p);
                            float sn, cs;
                            sincosf(ang, &sn, &cs);
                            float v1 = vals[j][s] * r, v2 = vals[j + 4][s] * r;
                            o1[s] = v1 * cs + v2 * sn;
                            o2[s] = v2 * cs - v1 * sn;
                        }
                        int c0 = (lane & 3) * 2 + j * 8;
                        if (hd < 16) {
                            size_t base = ((size_t)(bb * 16 + hd) * 2048 + t) * 64;
                            *(uint32_t*)(qh + base + c0)      = pack2h(o1[0], o1[1]);
                            *(uint32_t*)(qh + base + c0 + 32) = pack2h(o2[0], o2[1]);
                        } else {
                            size_t base = ((size_t)(bb * 4 + hd - 16) * 2048 + t) * 64;
                            *(uint32_t*)(kh + base + c0)      = pack2h(o1[0], o1[1]);
                            *(uint32_t*)(kh + base + c0 + 32) = pack2h(o2[0], o2[1]);
                        }
                    }
                } else {
                    size_t base = ((size_t)(bb * 4 + hd - 20) * 2048 + t) * 64;
#pragma unroll
                    for (int j = 0; j < 8; j++) {
                        int c0 = (lane & 3) * 2 + j * 8;
                        *(uint32_t*)(vh + base + c0) = pack2h(vals[j][0], vals[j][1]);
                    }
                }
            }
        }
        return;
    }

#pragma unroll
    for (int i = 0; i < 2; i++) {
#pragma unroll
        for (int half = 0; half < 2; half++) {
            size_t row = (size_t)(rbase + i * 16 + half * 8);
#pragma unroll
            for (int j = 0; j < 8; j++) {
                size_t idx = row * (size_t)N + cbase + j * 8;
                float v0 = acc[i][j][half * 2 + 0];
                float v1 = acc[i][j][half * 2 + 1];
                if (mode == 1) {
                    v0 = fmaxf(v0, 0.f); v0 *= v0;
                    v1 = fmaxf(v1, 0.f); v1 *= v1;
                    *(uint32_t*)(OH + idx) = pack2h(v0, v1);
                } else {
                    if (res) { v0 += res[idx]; v1 += res[idx + 1]; }
                    *(float2*)(C + idx) = make_float2(v0, v1);
                }
            }
        }
    }
}

// ---------------- RMSNorm with fp16 output ----------------
__global__ void rmsnorm_h_kernel(const float* __restrict__ x, __half* __restrict__ hi)
{
    int n = blockIdx.x;
    int tid = threadIdx.x;
    const float4* xr = (const float4*)(x + (size_t)n * 1024);
    float4 v = xr[tid];
    float s = v.x*v.x + v.y*v.y + v.z*v.z + v.w*v.w;
#pragma unroll
    for (int off = 16; off > 0; off >>= 1) s += __shfl_xor_sync(0xffffffffu, s, off);
    __shared__ float red[8];
    if ((tid & 31) == 0) red[tid >> 5] = s;
    __syncthreads();
    float tot = 0.f;
#pragma unroll
    for (int i = 0; i < 8; i++) tot += red[i];
    float r = rsqrtf(tot * (1.f/1024.f) + 1e-6f);
    size_t base = (size_t)n * 1024 + tid * 4;
    *(uint2*)(hi + base) = make_uint2(pack2h(v.x*r, v.y*r), pack2h(v.z*r, v.w*r));
}

// ---------------- tensor-core flash attention (fp16, Q tile = 128 rows) ----------------
#define AT_ROWB 144
#define AT_TILE (64 * AT_ROWB)
#define AQ_BYTES (2 * AT_TILE)
#define AT_STAGE (2 * AT_TILE)
#define ATTN_SMEM (AQ_BYTES + 2 * AT_STAGE)

__device__ __forceinline__ void attn_load_kv(
    uint32_t dstbase, int tid,
    const __half* kh, const __half* vh, size_t kvoff, int kt)
{
#pragma unroll
    for (int t = 0; t < 4; t++) {
        int idx = tid + 256 * t;
        int buf = idx >> 9, cc = idx & 511, row = cc >> 3, ch = cc & 7;
        const __half* src = (buf ? vh : kh) + kvoff + (size_t)(kt * 64 + row) * 64 + ch * 8;
        CP_ASYNC16(dstbase + buf * AT_TILE + row * AT_ROWB + ch * 16, src);
    }
}

__global__ __launch_bounds__(256) void attn_mma_kernel(
    const __half* __restrict__ qh,
    const __half* __restrict__ kh, const __half* __restrict__ vh,
    __half* __restrict__ yh)
{
    extern __shared__ char smem[];
    uint32_t sb = smem_u32(smem);
    int qt = gridDim.x - 1 - blockIdx.x;
    int h = blockIdx.y, b = blockIdx.z;
    int tid = threadIdx.x, w = tid >> 5, lane = tid & 31;
    int lr = lane & 7, lt = lane >> 3;
    size_t qoff = ((size_t)(b * 16 + h) * 2048 + qt * 128) * 64;
    size_t kvoff = (size_t)(b * 4 + (h >> 2)) * 2048 * 64;

#pragma unroll
    for (int t = 0; t < 4; t++) {
        int idx = tid + 256 * t;
        int row = idx >> 3, ch = idx & 7;
        CP_ASYNC16(sb + row * AT_ROWB + ch * 16, qh + qoff + row * 64 + ch * 8);
    }
    CP_COMMIT();
    attn_load_kv(sb + AQ_BYTES, tid, kh, vh, kvoff, 0);
    CP_COMMIT();
    CP_WAIT0();
    __syncthreads();

    uint32_t qfh[4][4];
#pragma unroll
    for (int kk = 0; kk < 4; kk++) {
        uint32_t addr = sb + (w * 16 + lr + (lt & 1) * 8) * AT_ROWB + (kk * 16 + (lt >> 1) * 8) * 2;
        LDSM_X4(qfh[kk], addr);
    }

    float O[8][4];
#pragma unroll
    for (int j = 0; j < 8; j++)
#pragma unroll
        for (int r = 0; r < 4; r++) O[j][r] = 0.f;
    float m0 = -1e30f, m1 = -1e30f, l0 = 0.f, l1 = 0.f;

    int ktmax = 2 * qt + 1;
    int grow0 = qt * 128 + w * 16 + (lane >> 2);
    int grow1 = grow0 + 8;

    for (int kt = 0; kt <= ktmax; kt++) {
        if (kt < ktmax) {
            attn_load_kv(sb + AQ_BYTES + ((kt + 1) & 1) * AT_STAGE, tid, kh, vh, kvoff, kt + 1);
            CP_COMMIT();
        }
        uint32_t kb = sb + AQ_BYTES + (kt & 1) * AT_STAGE;
        float c[8][4];
#pragma unroll
        for (int j = 0; j < 8; j++)
#pragma unroll
            for (int r = 0; r < 4; r++) c[j][r] = 0.f;
#pragma unroll
        for (int kk = 0; kk < 4; kk++) {
            uint32_t kbh[4][4];
#pragma unroll
            for (int j2 = 0; j2 < 4; j2++) {
                uint32_t addr = kb + (j2 * 16 + lr + (lt >> 1) * 8) * AT_ROWB + (kk * 16 + (lt & 1) * 8) * 2;
                LDSM_X4(kbh[j2], addr);
            }
#pragma unroll
            for (int j = 0; j < 8; j++) {
                MMA_FP16(c[j], qfh[kk], kbh[j >> 1][(j & 1) * 2], kbh[j >> 1][(j & 1) * 2 + 1]);
            }
        }
        if (kt >= 2 * qt) {
#pragma unroll
            for (int j = 0; j < 8; j++) {
                int gcol = kt * 64 + j * 8 + (lane & 3) * 2;
                if (gcol     > grow0) c[j][0] = -1e30f;
                if (gcol + 1 > grow0) c[j][1] = -1e30f;
                if (gcol     > grow1) c[j][2] = -1e30f;
                if (gcol + 1 > grow1) c[j][3] = -1e30f;
            }
        }
        float mx0 = -1e30f, mx1 = -1e30f;
#pragma unroll
        for (int j = 0; j < 8; j++) {
            mx0 = fmaxf(mx0, fmaxf(c[j][0], c[j][1]));
            mx1 = fmaxf(mx1, fmaxf(c[j][2], c[j][3]));
        }
        mx0 *= 0.125f; mx1 *= 0.125f;
        mx0 = fmaxf(mx0, __shfl_xor_sync(0xffffffffu, mx0, 1));
        mx0 = fmaxf(mx0, __shfl_xor_sync(0xffffffffu, mx0, 2));
        mx1 = fmaxf(mx1, __shfl_xor_sync(0xffffffffu, mx1, 1));
        mx1 = fmaxf(mx1, __shfl_xor_sync(0xffffffffu, mx1, 2));
        float m0n = fmaxf(m0, mx0), m1n = fmaxf(m1, mx1);
        float cr0 = __expf(m0 - m0n), cr1 = __expf(m1 - m1n);
        float s0 = 0.f, s1 = 0.f;
#pragma unroll
        for (int j = 0; j < 8; j++) {
            c[j][0] = __expf(fmaf(c[j][0], 0.125f, -m0n)); s0 += c[j][0];
            c[j][1] = __expf(fmaf(c[j][1], 0.125f, -m0n)); s0 += c[j][1];
            c[j][2] = __expf(fmaf(c[j][2], 0.125f, -m1n)); s1 += c[j][2];
            c[j][3] = __expf(fmaf(c[j][3], 0.125f, -m1n)); s1 += c[j][3];
        }
        s0 += __shfl_xor_sync(0xffffffffu, s0, 1);
        s0 += __shfl_xor_sync(0xffffffffu, s0, 2);
        s1 += __shfl_xor_sync(0xffffffffu, s1, 1);
        s1 += __shfl_xor_sync(0xffffffffu, s1, 2);
        l0 = l0 * cr0 + s0; l1 = l1 * cr1 + s1;
        m0 = m0n; m1 = m1n;
#pragma unroll
        for (int j = 0; j < 8; j++) {
            O[j][0] *= cr0; O[j][1] *= cr0;
            O[j][2] *= cr1; O[j][3] *= cr1;
        }
#pragma unroll
        for (int kt2 = 0; kt2 < 4; kt2++) {
            uint32_t pah[4];
            pah[0] = pack2h(c[2*kt2][0],   c[2*kt2][1]);
            pah[1] = pack2h(c[2*kt2][2],   c[2*kt2][3]);
            pah[2] = pack2h(c[2*kt2+1][0], c[2*kt2+1][1]);
            pah[3] = pack2h(c[2*kt2+1][2], c[2*kt2+1][3]);
#pragma unroll
            for (int jd = 0; jd < 4; jd++) {
                uint32_t vbh[4];
                uint32_t addr = kb + AT_TILE + (kt2 * 16 + (lt & 1) * 8 + lr) * AT_ROWB + (jd * 16 + (lt >> 1) * 8) * 2;
                LDSM_X4_T(vbh, addr);
#pragma unroll
                for (int js = 0; js < 2; js++) {
                    MMA_FP16(O[jd * 2 + js], pah, vbh[js*2], vbh[js*2+1]);
                }
            }
        }
        if (kt < ktmax) CP_WAIT0();
        __syncthreads();
    }
    float i0 = 1.f / l0, i1 = 1.f / l1;
    size_t rA = (size_t)(b * 2048 + qt * 128 + w * 16 + (lane >> 2));
    size_t rB = rA + 8;
    int colb = h * 64 + (lane & 3) * 2;
#pragma unroll
    for (int j = 0; j < 8; j++) {
        int col = colb + j * 8;
        *(uint32_t*)(yh + rA * 1024 + col) = pack2h(O[j][0] * i0, O[j][1] * i0);
        *(uint32_t*)(yh + rB * 1024 + col) = pack2h(O[j][2] * i1, O[j][3] * i1);
    }
}

// ---------------- fold1 via HMMA: WM2T[j, G*64+D] = sum_C mix[G*64+C, j] * s2[G,C,D] ----------------
// smem: s2t [C][D] fp16 stride 72h, then 8 warp-private mix tiles [C][j] stride 72h
#define FROW 72
#define FROWB 144
#define FTILE (64 * FROWB)                  // 9216 B
#define FOLD1_SMEM (9 * FTILE)              // 82944

__global__ __launch_bounds__(256) void fold1_mma(
    const float* __restrict__ Mix, const float* __restrict__ S2,
    __half* __restrict__ WM2T, int in_f, int out_f,
    const int* __restrict__ selp)
{
    extern __shared__ __half sh[];
    uint32_t sbase = smem_u32(sh);
    int G = blockIdx.x, chunk = blockIdx.y, r = blockIdx.z;
    int sel = selp[r];
    int tid = threadIdx.x, w = tid >> 5, lane = tid & 31;
    int lr = lane & 7, lt = lane >> 3;

    // s2 tile [C][D] -> fp16
    const float* s2p = S2 + (size_t)sel * out_f * 64 + (size_t)G * 4096;
    for (int i = tid * 2; i < 4096; i += 512) {
        int C = i >> 6, D = i & 63;
        float2 v = *(const float2*)(s2p + i);
        *(uint32_t*)&sh[C * FROW + D] = pack2h(v.x, v.y);
    }
    // warp-private mix tile [C][j] -> fp16
    int jb = chunk * 8 + w;
    __half* mixt = sh + 4608 + w * 4608;
    const float* mp = Mix + (size_t)sel * out_f * in_f + (size_t)(G * 64) * in_f + jb * 64;
    for (int t = 0; t < 64; t++) {
        int i = lane * 2 + 64 * t;
        int C = i >> 6, j = i & 63;
        float2 v = *(const float2*)(mp + (size_t)C * in_f + j);
        *(uint32_t*)&mixt[C * FROW + j] = pack2h(v.x, v.y);
    }
    __syncthreads();

    uint32_t s2b = sbase;
    uint32_t mxb = sbase + (4608 + w * 4608) * 2;

    // B frags (trans) from s2t: B[n=D][k=C]
    uint32_t bfr[4][4][4];
#pragma unroll
    for (int kk = 0; kk < 4; kk++)
#pragma unroll
        for (int ng = 0; ng < 4; ng++) {
            uint32_t addr = s2b + (kk * 16 + (lt & 1) * 8 + lr) * FROWB + (ng * 16 + (lt >> 1) * 8) * 2;
            LDSM_X4_T(bfr[kk][ng], addr);
        }

    __half* outp = WM2T + (size_t)r * in_f * out_f;
#pragma unroll
    for (int mi = 0; mi < 4; mi++) {
        // A frags (trans) from mixt: A[m=j][k=C]
        uint32_t afr[4][4];
#pragma unroll
        for (int kk = 0; kk < 4; kk++) {
            uint32_t addr = mxb + (kk * 16 + (lt >> 1) * 8 + lr) * FROWB + (mi * 16 + (lt & 1) * 8) * 2;
            LDSM_X4_T(afr[kk], addr);
        }
        float acc[8][4];
#pragma unroll
        for (int n = 0; n < 8; n++)
#pragma unroll
            for (int q = 0; q < 4; q++) acc[n][q] = 0.f;
#pragma unroll
        for (int kk = 0; kk < 4; kk++)
#pragma unroll
            for (int ng = 0; ng < 4; ng++)
#pragma unroll
                for (int js = 0; js < 2; js++)
                    MMA_FP16(acc[ng * 2 + js], afr[kk], bfr[kk][ng][js * 2], bfr[kk][ng][js * 2 + 1]);
        int j0 = jb * 64 + mi * 16 + (lane >> 2);
#pragma unroll
        for (int n = 0; n < 8; n++) {
            int O = G * 64 + n * 8 + (lane & 3) * 2;
            *(uint32_t*)(outp + (size_t)j0 * out_f + O)       = pack2h(acc[n][0], acc[n][1]);
            *(uint32_t*)(outp + (size_t)(j0 + 8) * out_f + O) = pack2h(acc[n][2], acc[n][3]);
        }
    }
}

// ---------------- fold2 via HMMA: WH[O, g*64+c] = sum_r coef_r sum_d WM2T_r[d*n_in+gs_r, O] * s1_r[g,c,d] ----------------
// smem: A0 [d][O], A1 [d][O] (fp16 cp.async), B0 [c][d], B1 [c][d] (fp32->fp16), each 64xFROW
#define FOLD2_SMEM (4 * FTILE)              // 36864

__global__ __launch_bounds__(128) void fold2_mma(
    const __half* __restrict__ WM2T, const float* __restrict__ S1,
    __half* __restrict__ WH,
    int in_f, int out_f, int n_in,
    const int* __restrict__ selp, const float* __restrict__ coefp)
{
    extern __shared__ __half sh[];
    uint32_t sbase = smem_u32(sh);
    int g = blockIdx.x, Ob = blockIdx.y;
    int tid = threadIdx.x, w = tid >> 5, lane = tid & 31;
    int lr = lane & 7, lt = lane >> 3;
    int s0i = selp[0], s1i = selp[1];
    int gs0 = (g + s0i) % n_in, gs1 = (g + s1i) % n_in;

    // A tiles via cp.async: A_r[d][O] rows of 128B
#pragma unroll
    for (int t = 0; t < 8; t++) {
        int idx = tid + 128 * t;                // 0..1023
        int rr = idx >> 9, cc = idx & 511, d = cc >> 3, ch = cc & 7;
        int gs = rr ? gs1 : gs0;
        const __half* src = WM2T + (size_t)rr * in_f * out_f
                          + (size_t)(d * n_in + gs) * out_f + Ob * 64 + ch * 8;
        CP_ASYNC16(sbase + rr * FTILE + d * FROWB + ch * 16, src);
    }
    CP_COMMIT();
    // B tiles fp32 -> fp16: B_r[c][d] = s1[sel_r][g][c][d]
    for (int i = tid * 2; i < 8192; i += 256) {
        int rr = i >> 12, ii = i & 4095, c = ii >> 6, d = ii & 63;
        const float* sp = S1 + (size_t)(rr ? s1i : s0i) * in_f * 64 + (size_t)g * 4096 + c * 64 + d;
        float2 v = *(const float2*)sp;
        *(uint32_t*)&sh[(2 + rr) * (FTILE / 2) + c * FROW + d] = pack2h(v.x, v.y);
    }
    CP_WAIT0();
    __syncthreads();

    uint32_t a0b = sbase, a1b = sbase + FTILE;
    uint32_t b0b = sbase + 2 * FTILE, b1b = sbase + 3 * FTILE;

    float accA[8][4], accB[8][4];
#pragma unroll
    for (int n = 0; n < 8; n++)
#pragma unroll
        for (int q = 0; q < 4; q++) { accA[n][q] = 0.f; accB[n][q] = 0.f; }

#pragma unroll
    for (int kk = 0; kk < 4; kk++) {
        // A[m=O][k=d] trans from [d][O]
        uint32_t af0[4], af1[4];
        uint32_t arow = (kk * 16 + (lt >> 1) * 8 + lr) * FROWB + (w * 16 + (lt & 1) * 8) * 2;
        LDSM_X4_T(af0, a0b + arow);
        LDSM_X4_T(af1, a1b + arow);
#pragma unroll
        for (int ng = 0; ng < 4; ng++) {
            // B[n=c][k=d] non-trans from [c][d]
            uint32_t brow = (ng * 16 + lr + (lt >> 1) * 8) * FROWB + (kk * 16 + (lt & 1) * 8) * 2;
            uint32_t b0[4], b1[4];
            LDSM_X4(b0, b0b + brow);
            LDSM_X4(b1, b1b + brow);
#pragma unroll
            for (int js = 0; js < 2; js++) {
                MMA_FP16(accA[ng * 2 + js], af0, b0[js * 2], b0[js * 2 + 1]);
                MMA_FP16(accB[ng * 2 + js], af1, b1[js * 2], b1[js * 2 + 1]);
            }
        }
    }
    float c0 = coefp[0], c1 = coefp[1];
    int O0 = Ob * 64 + w * 16 + (lane >> 2);
#pragma unroll
    for (int n = 0; n < 8; n++) {
        int cc = g * 64 + n * 8 + (lane & 3) * 2;
        float v0 = c0 * accA[n][0] + c1 * accB[n][0];
        float v1 = c0 * accA[n][1] + c1 * accB[n][1];
        float v2 = c0 * accA[n][2] + c1 * accB[n][2];
        float v3 = c0 * accA[n][3] + c1 * accB[n][3];
        *(uint32_t*)(WH + (size_t)O0 * in_f + cc)       = pack2h(v0, v1);
        *(uint32_t*)(WH + (size_t)(O0 + 8) * in_f + cc) = pack2h(v2, v3);
    }
}

// ---------------- top-2 router ----------------
__global__ void router_kernel(const float* __restrict__ fcl, const float* __restrict__ pjl,
                              int* __restrict__ sel, float* __restrict__ coef)
{
    if (threadIdx.x == 0 && blockIdx.x == 0) {
#pragma unroll
        for (int s = 0; s < 2; s++) {
            const float* L = s ? pjl : fcl;
            int i1 = 0; float v1 = L[0];
            for (int i = 1; i < 8; i++) if (L[i] > v1) { v1 = L[i]; i1 = i; }
            int i2 = -1; float v2 = -1e30f;
            for (int i = 0; i < 8; i++) if (i != i1 && L[i] > v2) { v2 = L[i]; i2 = i; }
            float e = expf(v2 - v1);
            float z = 1.f + e;
            sel[s*2+0] = i1; sel[s*2+1] = i2;
            coef[s*2+0] = 1.f / z; coef[s*2+1] = e / z;
        }
    }
}

// ---------------- host orchestration ----------------
extern "C" void kernel_launch(void* const* d_in, const int* in_sizes, int n_in_,
                              void* d_out, int out_size)
{
    (void)in_sizes; (void)n_in_; (void)out_size;
    const float* x      = (const float*)d_in[0];
    const float* wq     = (const float*)d_in[1];
    const float* wk     = (const float*)d_in[2];
    const float* wv     = (const float*)d_in[3];
    const float* wo     = (const float*)d_in[4];
    const float* qg     = (const float*)d_in[5];
    const float* kg     = (const float*)d_in[6];
    const float* fc_s1  = (const float*)d_in[7];
    const float* fc_s2  = (const float*)d_in[8];
    const float* fc_mix = (const float*)d_in[9];
    const float* fc_lg  = (const float*)d_in[10];
    const float* pj_s1  = (const float*)d_in[11];
    const float* pj_s2  = (const float*)d_in[12];
    const float* pj_mix = (const float*)d_in[13];
    const float* pj_lg  = (const float*)d_in[14];

    float *x2, *coef;
    int* sel;
    __half *wm0, *wm1, *ah, *gh, *wh, *who, *wfch, *wpjh, *yh, *qh, *kh, *vh;
    cudaGetSymbolAddress((void**)&x2,  g_x2);
    cudaGetSymbolAddress((void**)&wm0, g_wm0);
    cudaGetSymbolAddress((void**)&wm1, g_wm1);
    cudaGetSymbolAddress((void**)&sel,  g_sel);
    cudaGetSymbolAddress((void**)&coef, g_coef);
    cudaGetSymbolAddress((void**)&ah, g_ah);
    cudaGetSymbolAddress((void**)&gh, g_gh);
    cudaGetSymbolAddress((void**)&wh, g_wh);
    cudaGetSymbolAddress((void**)&who, g_who);
    cudaGetSymbolAddress((void**)&wfch, g_wfch);
    cudaGetSymbolAddress((void**)&wpjh, g_wpjh);
    cudaGetSymbolAddress((void**)&yh, g_yh);
    cudaGetSymbolAddress((void**)&qh, g_qh);
    cudaGetSymbolAddress((void**)&kh, g_kh);
    cudaGetSymbolAddress((void**)&vh, g_vh);

    cudaFuncSetAttribute(gemm_fp16, cudaFuncAttributeMaxDynamicSharedMemorySize, GEMM_SMEM);
    cudaFuncSetAttribute(attn_mma_kernel, cudaFuncAttributeMaxDynamicSharedMemorySize, ATTN_SMEM);
    cudaFuncSetAttribute(fold1_mma, cudaFuncAttributeMaxDynamicSharedMemorySize, FOLD1_SMEM);
    cudaFuncSetAttribute(fold2_mma, cudaFuncAttributeMaxDynamicSharedMemorySize, FOLD2_SMEM);

    static cudaStream_t s2 = nullptr;
    static cudaEvent_t ev_fork = nullptr, ev_wqkv = nullptr, ev_wo = nullptr, ev_fold = nullptr;
    if (!s2) {
        cudaStreamCreateWithFlags(&s2, cudaStreamNonBlocking);
        cudaEventCreateWithFlags(&ev_fork, cudaEventDisableTiming);
        cudaEventCreateWithFlags(&ev_wqkv, cudaEventDisableTiming);
        cudaEventCreateWithFlags(&ev_wo,   cudaEventDisableTiming);
        cudaEventCreateWithFlags(&ev_fold, cudaEventDisableTiming);
    }

    // ---- fork: side stream does weight converts + routing + folding (tensor-core folds) ----
    cudaEventRecord(ev_fork, 0);
    cudaStreamWaitEvent(s2, ev_fork, 0);

    splith_kernel<<<512, 256, 0, s2>>>(wq, wh, 1048576);
    splith_kernel<<<128, 256, 0, s2>>>(wk, wh + 1048576, 262144);
    splith_kernel<<<128, 256, 0, s2>>>(wv, wh + 1310720, 262144);
    cudaEventRecord(ev_wqkv, s2);
    splith_kernel<<<512, 256, 0, s2>>>(wo, who, 1048576);
    cudaEventRecord(ev_wo, s2);
    router_kernel<<<1, 32, 0, s2>>>(fc_lg, pj_lg, sel, coef);
    // fc: in_f=1024 (16 jb -> 2 chunks), out_f=4096 (n_out=64)
    fold1_mma<<<dim3(64, 2, 2), 256, FOLD1_SMEM, s2>>>(fc_mix, fc_s2, wm0, 1024, 4096, sel);
    fold2_mma<<<dim3(16, 64), 128, FOLD2_SMEM, s2>>>(wm0, fc_s1, wfch, 1024, 4096, 16, sel, coef);
    // pj: in_f=4096 (64 jb -> 8 chunks), out_f=1024 (n_out=16)
    fold1_mma<<<dim3(16, 8, 2), 256, FOLD1_SMEM, s2>>>(pj_mix, pj_s2, wm1, 4096, 1024, sel + 2);
    fold2_mma<<<dim3(64, 16), 128, FOLD2_SMEM, s2>>>(wm1, pj_s1, wpjh, 4096, 1024, 64, sel + 2, coef + 2);
    cudaEventRecord(ev_fold, s2);

    // ---- main stream: attention path ----
    rmsnorm_h_kernel<<<4096, 256>>>(x, ah);
    cudaStreamWaitEvent(0, ev_wqkv, 0);
    gemm_fp16<<<dim3(12, 32), 256, GEMM_SMEM>>>(ah, wh, nullptr, nullptr, 1536, 1024,
                                                nullptr, 2, qh, kh, vh, qg, kg);
    attn_mma_kernel<<<dim3(16, 16, 2), 256, ATTN_SMEM>>>(qh, kh, vh, yh);

    cudaStreamWaitEvent(0, ev_wo, 0);
    gemm_fp16<<<dim3(8, 32), 256, GEMM_SMEM>>>(yh, who, x2, x, 1024, 1024,
                                               nullptr, 0, nullptr, nullptr, nullptr, nullptr, nullptr);

    rmsnorm_h_kernel<<<4096, 256>>>(x2, ah);

    cudaStreamWaitEvent(0, ev_fold, 0);
    gemm_fp16<<<dim3(32, 32), 256, GEMM_SMEM>>>(ah, wfch, nullptr, nullptr, 4096, 1024,
                                                gh, 1, nullptr, nullptr, nullptr, nullptr, nullptr);
    gemm_fp16<<<dim3(8, 32), 256, GEMM_SMEM>>>(gh, wpjh, (float*)d_out, x2, 1024, 4096,
                                               nullptr, 0, nullptr, nullptr, nullptr, nullptr, nullptr);
}